// round 5
// baseline (speedup 1.0000x reference)
#include <cuda_runtime.h>

#define OBS   20
#define PRED  30
#define B_AG  32768
#define ROW2  65536       // B*2 (flat row size of (t, B, 2))
#define HD    64
#define ED    16
#define KD    80          // E + H
#define NG    256         // 4H
#define AB    64          // agents per block
#define NTHR  512
#define NBLK  (B_AG / AB) // 512
#define XH_STR 68         // padded stride for sXH [k][a]
#define HB_STR 72         // padded stride for hbuf [a][j]

#define WROWS 84          // 80 W rows + 1 bias row + 3 pad
#define WFLOATS (WROWS * NG)   // 21504 floats = 86016 B = 5376 x 16B chunks
#define SMALLN 1024

// persistent state + prepped params (device scratch; no runtime allocation)
__device__ __align__(16) float g_h[B_AG * HD];
__device__ __align__(16) float g_c[B_AG * HD];
__device__ __align__(16) float g_prep[WFLOATS];   // [k][n] transposed W, row 80 = b_ih+b_hh
__device__ __align__(16) float g_smalls[SMALLN];

// ---- packed fp32x2 helpers (Blackwell 2xFP32, PTX-only) ----
__device__ __forceinline__ unsigned long long dup2(float x) {
    unsigned long long r; unsigned u = __float_as_uint(x);
    asm("mov.b64 %0, {%1, %1};" : "=l"(r) : "r"(u));
    return r;
}
__device__ __forceinline__ void fma2(unsigned long long& d,
                                     unsigned long long a,
                                     unsigned long long b) {
    asm("fma.rn.f32x2 %0, %1, %2, %0;" : "+l"(d) : "l"(a), "l"(b));
}
__device__ __forceinline__ float2 unpk(unsigned long long v) {
    float lo, hi;
    asm("mov.b64 {%0, %1}, %2;" : "=f"(lo), "=f"(hi) : "l"(v));
    return make_float2(lo, hi);
}
__device__ __forceinline__ void cp16(unsigned s, const void* g) {
    asm volatile("cp.async.cg.shared.global [%0], [%1], 16;" :: "r"(s), "l"(g));
}

__device__ __forceinline__ float sigm(float x) {
    float e = __expf(-x);
    return __fdividef(1.f, 1.f + e);
}
__device__ __forceinline__ float tanh_(float x) {
    float e = __expf(-2.f * x);
    return __fdividef(2.f, 1.f + e) - 1.f;
}

// ---------------- one-time prep: transpose W, pack smalls, init state ----------------
__global__ void prep_kernel(const float* __restrict__ decoderH,
                            const float* __restrict__ W_ih, const float* __restrict__ W_hh,
                            const float* __restrict__ b_ih, const float* __restrict__ b_hh,
                            const float* __restrict__ embW, const float* __restrict__ embB,
                            const float* __restrict__ ln1g, const float* __restrict__ ln1b,
                            const float* __restrict__ ln2g, const float* __restrict__ ln2b,
                            const float* __restrict__ h2pW, const float* __restrict__ h2pB)
{
    const int gid = blockIdx.x * blockDim.x + threadIdx.x;
    if (gid < WFLOATS) {
        const int k = gid >> 8;
        const int n = gid & 255;
        float v;
        if (k < ED)            v = W_ih[n * ED + k];
        else if (k < KD)       v = W_hh[n * HD + (k - ED)];
        else if (k == KD)      v = b_ih[n] + b_hh[n];
        else                   v = 0.f;
        g_prep[gid] = v;
    }
    if (gid < SMALLN) {
        float v;
        if (gid < 640)       v = embW[gid];
        else if (gid < 656)  v = embB[gid - 640];
        else if (gid < 696)  v = ln1g[gid - 656];
        else if (gid < 736)  v = ln1b[gid - 696];
        else if (gid < 800)  v = ln2g[gid - 736];
        else if (gid < 864)  v = ln2b[gid - 800];
        else if (gid < 992)  v = h2pW[gid - 864];
        else if (gid < 994)  v = h2pB[gid - 992];
        else                 v = 0.f;
        g_smalls[gid] = v;
    }
    if (gid < B_AG * HD) {
        g_h[gid] = decoderH[gid];
        g_c[gid] = 0.f;
    }
}

// ---------------- per-step fused kernel (512 threads) ----------------
__global__ void __launch_bounds__(NTHR, 2)
lstm_step(int s,
          const float* __restrict__ trajAbs,
          float* __restrict__ out)
{
    extern __shared__ float sm[];
    float* sW    = sm;                 // [k][256], row 80 = bias
    float* sXH   = sm + WFLOATS;       // [80][68]
    float* sSm   = sXH + 5440;         // 1024 small params
    float* sBias = sW + KD * NG;       // row 80
    float* sEmbW = sSm;                // 640
    float* sEmbB = sSm + 640;          // 16
    float* sLn1g = sSm + 656;          // 40
    float* sLn1b = sSm + 696;          // 40
    float* sLn2g = sSm + 736;          // 64
    float* sLn2b = sSm + 800;          // 64
    float* sH2p  = sSm + 864;          // 128
    float* hbuf  = sW;                 // alias (rows 0..79 region; bias row 80 untouched)

    const int tid = threadIdx.x;
    const int b0  = blockIdx.x * AB;

    // async weight copy (overlaps with phase 1): 5376 x 16B chunks
    {
        unsigned sw_addr = (unsigned)__cvta_generic_to_shared(sW);
#pragma unroll
        for (int i = 0; i < 11; i++) {
            int c = tid + i * NTHR;
            if (c < 5376) cp16(sw_addr + c * 16, (const char*)g_prep + c * 16);
        }
        asm volatile("cp.async.commit_group;");
    }
    if (tid < 256) ((float4*)sSm)[tid] = ((const float4*)g_smalls)[tid];
    __syncthreads();

    // ---------------- phase 1: gather + LN1 + embed + leaky_relu ----------------
    // 8 threads per agent (jt = 0..7), 5 features each.
    {
        const int a  = tid >> 3;
        const int jt = tid & 7;
        const int b  = b0 + a;
        const int fbase = b * 40 + jt * 5;
        float raw[5];
#pragma unroll
        for (int u = 0; u < 5; u++) {
            int f   = fbase + u;
            int t   = f >> 16;          // logical timestep (B*2 == 65536)
            int rem = f & 65535;
            int row = s + t;            // rolled buffer: traj_abs[s:] ++ pred[:s]
            raw[u] = (row < OBS) ? trajAbs[row * ROW2 + rem]
                                 : out[(row - OBS) * ROW2 + rem];
        }
        float sum = 0.f, sq = 0.f;
#pragma unroll
        for (int u = 0; u < 5; u++) { sum += raw[u]; sq += raw[u] * raw[u]; }
#pragma unroll
        for (int m = 1; m < 8; m <<= 1) {
            sum += __shfl_xor_sync(0xffffffffu, sum, m);
            sq  += __shfl_xor_sync(0xffffffffu, sq, m);
        }
        const float mean = sum * 0.025f;
        const float var  = sq * 0.025f - mean * mean;
        const float rstd = rsqrtf(var + 1e-5f);

        float p[16];
#pragma unroll
        for (int e = 0; e < 16; e++) p[e] = 0.f;
#pragma unroll
        for (int u = 0; u < 5; u++) {
            int idx = jt * 5 + u;
            float xn = (raw[u] - mean) * rstd * sLn1g[idx] + sLn1b[idx];
#pragma unroll
            for (int e = 0; e < 16; e++) p[e] += xn * sEmbW[e * 40 + idx];
        }
#pragma unroll
        for (int e = 0; e < 16; e++) {
#pragma unroll
            for (int m = 1; m < 8; m <<= 1)
                p[e] += __shfl_xor_sync(0xffffffffu, p[e], m);
        }
#pragma unroll
        for (int i = 0; i < 2; i++) {
            int e = jt * 2 + i;
            float v = p[e] + sEmbB[e];
            v = v > 0.f ? v : 0.01f * v;   // leaky_relu(0.01)
            sXH[e * XH_STR + a] = v;
        }
    }
    // h tile load (coalesced read, padded-stride smem write): 4096 floats
    {
#pragma unroll
        for (int r = 0; r < 8; r++) {
            int idx = tid + r * NTHR;
            int j = idx & 63;
            int a = idx >> 6;
            sXH[(ED + j) * XH_STR + a] = g_h[(b0 + a) * HD + j];
        }
    }
    asm volatile("cp.async.wait_group 0;");
    __syncthreads();

    // ---------------- phase 2: gates GEMM (f32x2 packed) ----------------
    // thread tile: one column-pair per gate type (j = 2*tx, 2*tx+1) x 4 agents
    const int tx = tid & 31;
    const int ty = tid >> 5;        // 0..15
    unsigned long long acc[4][4];   // [gate][agent]
#pragma unroll
    for (int g = 0; g < 4; g++)
#pragma unroll
        for (int ai = 0; ai < 4; ai++) acc[g][ai] = 0ull;

    const float* xp = sXH + 4 * ty;
    const float* wp = sW + 2 * tx;
#pragma unroll 4
    for (int k = 0; k < KD; k++) {
        float4 xv = *(const float4*)(xp + k * XH_STR);   // warp-broadcast
        unsigned long long xx[4];
        xx[0] = dup2(xv.x); xx[1] = dup2(xv.y);
        xx[2] = dup2(xv.z); xx[3] = dup2(xv.w);
#pragma unroll
        for (int g = 0; g < 4; g++) {
            unsigned long long wv = *(const unsigned long long*)(wp + k * NG + 64 * g);
#pragma unroll
            for (int ai = 0; ai < 4; ai++)
                fma2(acc[g][ai], wv, xx[ai]);
        }
    }
    __syncthreads();   // all sW reads done before hbuf (alias) is written

    // ---------------- phase 3: LSTM cell (2 hidden units x 4 agents per thread) ----
    {
        float2 bb[4];
#pragma unroll
        for (int g = 0; g < 4; g++)
            bb[g] = *(const float2*)(sBias + g * 64 + 2 * tx);
#pragma unroll
        for (int ai = 0; ai < 4; ai++) {
            const int a = 4 * ty + ai;
            const int b = b0 + a;
            float2 cv = *(const float2*)(g_c + b * HD + 2 * tx);
            float cold[2] = {cv.x, cv.y};
            float gate[4][2];
#pragma unroll
            for (int g = 0; g < 4; g++) {
                float2 u = unpk(acc[g][ai]);
                gate[g][0] = u.x + bb[g].x;
                gate[g][1] = u.y + bb[g].y;
            }
            float2 cn, hn;
            float* cnp = &cn.x; float* hnp = &hn.x;
#pragma unroll
            for (int q = 0; q < 2; q++) {
                float ig = sigm(gate[0][q]);
                float fg = sigm(gate[1][q]);
                float gg = tanh_(gate[2][q]);
                float og = sigm(gate[3][q]);
                float c2 = fg * cold[q] + ig * gg;
                cnp[q] = c2;
                hnp[q] = og * tanh_(c2);
            }
            *(float2*)(g_c + b * HD + 2 * tx) = cn;
            *(float2*)(g_h + b * HD + 2 * tx) = hn;
            *(float2*)(hbuf + a * HB_STR + 2 * tx) = hn;
        }
    }
    __syncthreads();

    // ---------------- phase 4: LN2 + hidden2pos ----------------
    {
        const int a  = tid >> 3;
        const int jt = tid & 7;
        float hv[8];
        const float* hp = hbuf + a * HB_STR + jt * 8;
        {
            float4 v0 = *(const float4*)(hp);
            float4 v1 = *(const float4*)(hp + 4);
            hv[0]=v0.x; hv[1]=v0.y; hv[2]=v0.z; hv[3]=v0.w;
            hv[4]=v1.x; hv[5]=v1.y; hv[6]=v1.z; hv[7]=v1.w;
        }
        float sum = 0.f, sq = 0.f;
#pragma unroll
        for (int u = 0; u < 8; u++) { sum += hv[u]; sq += hv[u] * hv[u]; }
#pragma unroll
        for (int m = 1; m < 8; m <<= 1) {
            sum += __shfl_xor_sync(0xffffffffu, sum, m);
            sq  += __shfl_xor_sync(0xffffffffu, sq, m);
        }
        const float mean = sum * 0.015625f;
        const float var  = sq * 0.015625f - mean * mean;
        const float rstd = rsqrtf(var + 1e-5f);
        float p0 = 0.f, p1 = 0.f;
#pragma unroll
        for (int u = 0; u < 8; u++) {
            int j = jt * 8 + u;
            float xn = (hv[u] - mean) * rstd * sLn2g[j] + sLn2b[j];
            p0 += xn * sH2p[j];
            p1 += xn * sH2p[64 + j];
        }
#pragma unroll
        for (int m = 1; m < 8; m <<= 1) {
            p0 += __shfl_xor_sync(0xffffffffu, p0, m);
            p1 += __shfl_xor_sync(0xffffffffu, p1, m);
        }
        if (jt == 0) {
            float2 r = make_float2(p0 + sSm[992], p1 + sSm[993]);
            *(float2*)(out + s * ROW2 + (b0 + a) * 2) = r;
        }
    }
}

extern "C" void kernel_launch(void* const* d_in, const int* in_sizes, int n_in,
                              void* d_out, int out_size)
{
    const float* trajAbs  = (const float*)d_in[0];
    // d_in[1] = traj_rel (unused: use_rel_disp=False branch)
    const float* decoderH = (const float*)d_in[2];
    const float* W_ih = (const float*)d_in[3];
    const float* W_hh = (const float*)d_in[4];
    const float* b_ih = (const float*)d_in[5];
    const float* b_hh = (const float*)d_in[6];
    const float* embW = (const float*)d_in[7];
    const float* embB = (const float*)d_in[8];
    const float* h2pW = (const float*)d_in[9];
    const float* h2pB = (const float*)d_in[10];
    const float* ln1g = (const float*)d_in[11];
    const float* ln1b = (const float*)d_in[12];
    const float* ln2g = (const float*)d_in[13];
    const float* ln2b = (const float*)d_in[14];
    float* out = (float*)d_out;

    // argument order matches prep_kernel's signature exactly
    prep_kernel<<<(B_AG * HD + 255) / 256, 256>>>(
        decoderH, W_ih, W_hh, b_ih, b_hh, embW, embB,
        ln1g, ln1b, ln2g, ln2b, h2pW, h2pB);

    const int smemBytes = (WFLOATS + 5440 + SMALLN) * 4;  // 111872 B
    cudaFuncSetAttribute(lstm_step, cudaFuncAttributeMaxDynamicSharedMemorySize,
                         smemBytes);

    for (int s = 0; s < PRED; s++) {
        lstm_step<<<NBLK, NTHR, smemBytes>>>(s, trajAbs, out);
    }
}

// round 7
// speedup vs baseline: 1.4710x; 1.4710x over previous
#include <cuda_runtime.h>
#include <cuda_bf16.h>
#include <cstring>

#define OBS   20
#define PRED  30
#define B_AG  32768
#define ROW2  65536
#define HD    64
#define ED    16
#define KD    80
#define NG    256
#define AB    256               // agents per block
#define NTHR  512
#define NBLK  (B_AG / AB)       // 128  -> one wave on 148 SMs
#define KSTR  86                // bf16 row stride (43 words: conflict-free)

// ---- smem byte layout ----
#define SM_WHI   0                       // 256*86*2 = 44032
#define SM_WLO   44032                   // 44032
#define SM_AHI   88064                   // 44032
#define SM_ALO   132096                  // 44032
#define SM_SMALL 176128                  // 1280 floats = 5120 B
#define SM_TOTAL 181248
// smalls float offsets
#define O_EMBW 0
#define O_EMBB 640
#define O_LN1G 656
#define O_LN1B 696
#define O_LN2G 736
#define O_LN2B 800
#define O_H2P  864
#define O_H2PB 992
#define O_BIAS 1024   // 256 floats, gate-interleaved (n' = 4j+gate)
// hbuf aliases A region after GEMM: [a][j], stride 68 floats
#define HB_STR 68

// persistent state + prepped params. h/c stored [j][agent] (j-major).
__device__ __align__(16) float          g_h[HD * B_AG];
__device__ __align__(16) float          g_c[HD * B_AG];
__device__ __align__(16) unsigned short g_Whi[NG * KSTR];   // bf16 raw, row n' (gate-interleaved)
__device__ __align__(16) unsigned short g_Wlo[NG * KSTR];
__device__ __align__(16) float          g_smalls[1280];

// ---- helpers ----
__device__ __forceinline__ void cp16(unsigned s, const void* g) {
    asm volatile("cp.async.cg.shared.global [%0], [%1], 16;" :: "r"(s), "l"(g));
}
__device__ __forceinline__ unsigned pkbf(float a, float b) {
    __nv_bfloat162 t = __floats2bfloat162_rn(a, b);
    unsigned u; memcpy(&u, &t, 4); return u;
}
__device__ __forceinline__ void split(float v, float& hi, float& lo) {
    __nv_bfloat16 h = __float2bfloat16(v);
    hi = __bfloat162float(h);
    lo = v - hi;
}
__device__ __forceinline__ float sigm(float x) {
    float e = __expf(-x);
    return __fdividef(1.f, 1.f + e);
}
__device__ __forceinline__ float tanh_(float x) {
    float e = __expf(-2.f * x);
    return __fdividef(2.f, 1.f + e) - 1.f;
}
__device__ __forceinline__ void mma16816(float& d0, float& d1, float& d2, float& d3,
                                         unsigned a0, unsigned a1, unsigned a2, unsigned a3,
                                         unsigned b0, unsigned b1) {
    asm volatile(
        "mma.sync.aligned.m16n8k16.row.col.f32.bf16.bf16.f32 "
        "{%0,%1,%2,%3}, {%4,%5,%6,%7}, {%8,%9}, {%0,%1,%2,%3};"
        : "+f"(d0), "+f"(d1), "+f"(d2), "+f"(d3)
        : "r"(a0), "r"(a1), "r"(a2), "r"(a3), "r"(b0), "r"(b1));
}

// ---------------- one-time prep ----------------
__global__ void prep_kernel(const float* __restrict__ decoderH,
                            const float* __restrict__ W_ih, const float* __restrict__ W_hh,
                            const float* __restrict__ b_ih, const float* __restrict__ b_hh,
                            const float* __restrict__ embW, const float* __restrict__ embB,
                            const float* __restrict__ ln1g, const float* __restrict__ ln1b,
                            const float* __restrict__ ln2g, const float* __restrict__ ln2b,
                            const float* __restrict__ h2pW, const float* __restrict__ h2pB)
{
    const int gid = blockIdx.x * blockDim.x + threadIdx.x;
    // weights: n' = 4*j + gate  (gate-interleaved rows), k in [0,80)
    if (gid < NG * KD) {
        const int np = gid / KD;
        const int k  = gid % KD;
        const int gate = np & 3;
        const int j    = np >> 2;
        const int n    = gate * HD + j;
        float w = (k < ED) ? W_ih[n * ED + k] : W_hh[n * HD + (k - ED)];
        float hi, lo; split(w, hi, lo);
        __nv_bfloat16 hb = __float2bfloat16(hi);
        __nv_bfloat16 lb = __float2bfloat16(lo);
        unsigned short hs, ls; memcpy(&hs, &hb, 2); memcpy(&ls, &lb, 2);
        g_Whi[np * KSTR + k] = hs;
        g_Wlo[np * KSTR + k] = ls;
    }
    if (gid < 1280) {
        float v;
        if (gid < 640)       v = embW[gid];
        else if (gid < 656)  v = embB[gid - 640];
        else if (gid < 696)  v = ln1g[gid - 656];
        else if (gid < 736)  v = ln1b[gid - 696];
        else if (gid < 800)  v = ln2g[gid - 736];
        else if (gid < 864)  v = ln2b[gid - 800];
        else if (gid < 992)  v = h2pW[gid - 864];
        else if (gid < 994)  v = h2pB[gid - 992];
        else if (gid >= 1024) {
            int np = gid - 1024;             // interleaved bias
            int n  = (np & 3) * HD + (np >> 2);
            v = b_ih[n] + b_hh[n];
        }
        else                 v = 0.f;
        g_smalls[gid] = v;
    }
    // state, transposed to [j][b]
    if (gid < B_AG * HD) {
        const int j = gid >> 15;           // gid / 32768
        const int b = gid & 32767;
        g_h[gid] = decoderH[b * HD + j];
        g_c[gid] = 0.f;
    }
}

// ---------------- per-step kernel ----------------
__global__ void __launch_bounds__(NTHR, 1)
lstm_step(int s,
          const float* __restrict__ trajAbs,
          float* __restrict__ out)
{
    extern __shared__ char sm[];
    float* sSm   = (float*)(sm + SM_SMALL);
    float* sBias = sSm + O_BIAS;
    float* hbuf  = (float*)(sm + SM_AHI);   // alias, valid after A-frag preload

    const int tid  = threadIdx.x;
    const int wid  = tid >> 5;
    const int lane = tid & 31;
    const int b0   = blockIdx.x * AB;
    const unsigned sb = (unsigned)__cvta_generic_to_shared(sm);

    // kick W tile copies (88 KB total), overlap with phase 1
    {
#pragma unroll
        for (int i = 0; i < 6; i++) {
            int c = tid + i * NTHR;               // 2752 chunks per tile
            if (c < 2752) {
                cp16(sb + SM_WHI + c * 16, (const char*)g_Whi + c * 16);
                cp16(sb + SM_WLO + c * 16, (const char*)g_Wlo + c * 16);
            }
        }
        asm volatile("cp.async.commit_group;");
    }
    if (tid < 320) ((float4*)sSm)[tid] = ((const float4*)g_smalls)[tid];
    __syncthreads();

    // ---------------- phase 1: gather + LN1 + embed + leaky -> A cols 0..15 ----
    {
        const int a  = tid >> 1;
        const int jt = tid & 1;
        const int b  = b0 + a;
        const int fbase = b * 40 + jt * 20;
        float raw[20];
#pragma unroll
        for (int u = 0; u < 20; u++) {
            int f   = fbase + u;
            int t   = f >> 16;
            int rem = f & 65535;
            int row = s + t;
            raw[u] = (row < OBS) ? trajAbs[row * ROW2 + rem]
                                 : out[(row - OBS) * ROW2 + rem];
        }
        float sum = 0.f, sq = 0.f;
#pragma unroll
        for (int u = 0; u < 20; u++) { sum += raw[u]; sq += raw[u] * raw[u]; }
        sum += __shfl_xor_sync(0xffffffffu, sum, 1);
        sq  += __shfl_xor_sync(0xffffffffu, sq, 1);
        const float mean = sum * 0.025f;
        const float var  = sq * 0.025f - mean * mean;
        const float rstd = rsqrtf(var + 1e-5f);

        float p[16];
#pragma unroll
        for (int e = 0; e < 16; e++) p[e] = 0.f;
#pragma unroll
        for (int u = 0; u < 20; u++) {
            int idx = jt * 20 + u;
            float xn = (raw[u] - mean) * rstd * sSm[O_LN1G + idx] + sSm[O_LN1B + idx];
#pragma unroll
            for (int e = 0; e < 16; e++) p[e] += xn * sSm[O_EMBW + e * 40 + idx];
        }
#pragma unroll
        for (int e = 0; e < 16; e++)
            p[e] += __shfl_xor_sync(0xffffffffu, p[e], 1);

#pragma unroll
        for (int i = 0; i < 4; i++) {
            int e = jt * 8 + 2 * i;
            float v0 = p[e]   + sSm[O_EMBB + e];
            float v1 = p[e+1] + sSm[O_EMBB + e + 1];
            v0 = v0 > 0.f ? v0 : 0.01f * v0;
            v1 = v1 > 0.f ? v1 : 0.01f * v1;
            float h0, l0, h1, l1;
            split(v0, h0, l0); split(v1, h1, l1);
            unsigned off = a * (KSTR * 2) + e * 2;
            *(unsigned*)(sm + SM_AHI + off) = pkbf(h0, h1);
            *(unsigned*)(sm + SM_ALO + off) = pkbf(l0, l1);
        }
    }
    // h -> A cols 16..79 (8192 u32 writes; coalesced j-major reads)
    {
#pragma unroll
        for (int it = 0; it < 16; it++) {
            int idx = tid + it * NTHR;
            int a  = idx & 255;
            int j  = (idx >> 8) * 2;          // 0,2,..,62
            float v0 = g_h[j * B_AG + b0 + a];
            float v1 = g_h[(j + 1) * B_AG + b0 + a];
            float h0, l0, h1, l1;
            split(v0, h0, l0); split(v1, h1, l1);
            unsigned off = a * (KSTR * 2) + (16 + j) * 2;
            *(unsigned*)(sm + SM_AHI + off) = pkbf(h0, h1);
            *(unsigned*)(sm + SM_ALO + off) = pkbf(l0, l1);
        }
    }
    asm volatile("cp.async.wait_group 0;");
    __syncthreads();

    // ---------------- A-fragment preload (per-warp m-tile = wid) ----------------
    const int g   = lane >> 2;
    const int tig = lane & 3;
    unsigned ahi[5][4], alo[5][4];
    {
        const int r0 = wid * 16 + g;          // rows g, g+8 of this m-tile
#pragma unroll
        for (int kt = 0; kt < 5; kt++) {
            const int k0 = kt * 16 + 2 * tig;
            unsigned o00 = r0 * (KSTR * 2) + k0 * 2;
            unsigned o10 = o00 + 8 * (KSTR * 2);
            ahi[kt][0] = *(const unsigned*)(sm + SM_AHI + o00);
            ahi[kt][1] = *(const unsigned*)(sm + SM_AHI + o10);
            ahi[kt][2] = *(const unsigned*)(sm + SM_AHI + o00 + 16);
            ahi[kt][3] = *(const unsigned*)(sm + SM_AHI + o10 + 16);
            alo[kt][0] = *(const unsigned*)(sm + SM_ALO + o00);
            alo[kt][1] = *(const unsigned*)(sm + SM_ALO + o10);
            alo[kt][2] = *(const unsigned*)(sm + SM_ALO + o00 + 16);
            alo[kt][3] = *(const unsigned*)(sm + SM_ALO + o10 + 16);
        }
    }
    __syncthreads();   // A smem dead -> hbuf alias is now safe to write

    // ---------------- GEMM + fused LSTM cell, per n-tile ----------------
    const int oddp  = tig & 1;
    const int a_loc = wid * 16 + g + (oddp ? 8 : 0);
    const int bglob = b0 + a_loc;

#pragma unroll 1
    for (int nt = 0; nt < 32; nt++) {
        float d0 = 0.f, d1 = 0.f, d2 = 0.f, d3 = 0.f;
        const unsigned brow = (nt * 8 + g) * (KSTR * 2);
#pragma unroll
        for (int kt = 0; kt < 5; kt++) {
            const unsigned bo = brow + (kt * 16 + 2 * tig) * 2;
            unsigned bh0 = *(const unsigned*)(sm + SM_WHI + bo);
            unsigned bh1 = *(const unsigned*)(sm + SM_WHI + bo + 16);
            unsigned bl0 = *(const unsigned*)(sm + SM_WLO + bo);
            unsigned bl1 = *(const unsigned*)(sm + SM_WLO + bo + 16);
            mma16816(d0, d1, d2, d3, ahi[kt][0], ahi[kt][1], ahi[kt][2], ahi[kt][3], bh0, bh1);
            mma16816(d0, d1, d2, d3, ahi[kt][0], ahi[kt][1], ahi[kt][2], ahi[kt][3], bl0, bl1);
            mma16816(d0, d1, d2, d3, alo[kt][0], alo[kt][1], alo[kt][2], alo[kt][3], bh0, bh1);
        }
        // lane exchange: assemble one full (i,f,g,o) cell per lane
        float r0 = __shfl_xor_sync(0xffffffffu, d0, 1);
        float r1 = __shfl_xor_sync(0xffffffffu, d1, 1);
        float r2 = __shfl_xor_sync(0xffffffffu, d2, 1);
        float r3 = __shfl_xor_sync(0xffffffffu, d3, 1);
        float iv = oddp ? r2 : d0;
        float fv = oddp ? r3 : d1;
        float gv = oddp ? d2 : r0;
        float ov = oddp ? d3 : r1;
        const int jj = 2 * nt + (tig >> 1);
        float4 bias = *(const float4*)(sBias + 4 * jj);
        iv += bias.x; fv += bias.y; gv += bias.z; ov += bias.w;

        const int cidx = jj * B_AG + bglob;
        float c_old = g_c[cidx];
        float ig = sigm(iv);
        float fg = sigm(fv);
        float gg = tanh_(gv);
        float og = sigm(ov);
        float c2 = fg * c_old + ig * gg;
        float hv = og * tanh_(c2);
        g_c[cidx] = c2;
        g_h[cidx] = hv;
        hbuf[a_loc * HB_STR + jj] = hv;
    }
    __syncthreads();

    // ---------------- phase 4: LN2 + hidden2pos ----------------
    {
        const int a  = tid >> 1;
        const int jt = tid & 1;
        float hv[32];
        const float* hp = hbuf + a * HB_STR + jt * 32;
#pragma unroll
        for (int r = 0; r < 8; r++) {
            float4 v = *(const float4*)(hp + 4 * r);
            hv[4*r]=v.x; hv[4*r+1]=v.y; hv[4*r+2]=v.z; hv[4*r+3]=v.w;
        }
        float sum = 0.f, sq = 0.f;
#pragma unroll
        for (int u = 0; u < 32; u++) { sum += hv[u]; sq += hv[u] * hv[u]; }
        sum += __shfl_xor_sync(0xffffffffu, sum, 1);
        sq  += __shfl_xor_sync(0xffffffffu, sq, 1);
        const float mean = sum * 0.015625f;
        const float var  = sq * 0.015625f - mean * mean;
        const float rstd = rsqrtf(var + 1e-5f);
        float p0 = 0.f, p1 = 0.f;
#pragma unroll
        for (int u = 0; u < 32; u++) {
            int j = jt * 32 + u;
            float xn = (hv[u] - mean) * rstd * sSm[O_LN2G + j] + sSm[O_LN2B + j];
            p0 += xn * sSm[O_H2P + j];
            p1 += xn * sSm[O_H2P + 64 + j];
        }
        p0 += __shfl_xor_sync(0xffffffffu, p0, 1);
        p1 += __shfl_xor_sync(0xffffffffu, p1, 1);
        if (jt == 0) {
            float2 r = make_float2(p0 + sSm[O_H2PB], p1 + sSm[O_H2PB + 1]);
            *(float2*)(out + s * ROW2 + (b0 + a) * 2) = r;
        }
    }
}

extern "C" void kernel_launch(void* const* d_in, const int* in_sizes, int n_in,
                              void* d_out, int out_size)
{
    const float* trajAbs  = (const float*)d_in[0];
    const float* decoderH = (const float*)d_in[2];
    const float* W_ih = (const float*)d_in[3];
    const float* W_hh = (const float*)d_in[4];
    const float* b_ih = (const float*)d_in[5];
    const float* b_hh = (const float*)d_in[6];
    const float* embW = (const float*)d_in[7];
    const float* embB = (const float*)d_in[8];
    const float* h2pW = (const float*)d_in[9];
    const float* h2pB = (const float*)d_in[10];
    const float* ln1g = (const float*)d_in[11];
    const float* ln1b = (const float*)d_in[12];
    const float* ln2g = (const float*)d_in[13];
    const float* ln2b = (const float*)d_in[14];
    float* out = (float*)d_out;

    prep_kernel<<<(B_AG * HD + 255) / 256, 256>>>(
        decoderH, W_ih, W_hh, b_ih, b_hh, embW, embB,
        ln1g, ln1b, ln2g, ln2b, h2pW, h2pB);

    cudaFuncSetAttribute(lstm_step, cudaFuncAttributeMaxDynamicSharedMemorySize,
                         SM_TOTAL);

    for (int s = 0; s < PRED; s++) {
        lstm_step<<<NBLK, NTHR, SM_TOTAL>>>(s, trajAbs, out);
    }
}

// round 9
// speedup vs baseline: 2.1983x; 1.4944x over previous
#include <cuda_runtime.h>
#include <cuda_bf16.h>
#include <cstring>

#define OBS   20
#define PRED  30
#define B_AG  32768
#define ROW2  65536
#define HD    64
#define ED    16
#define KD    80
#define NG    256
#define AB    256               // agents per block
#define NTHR  512
#define NBLK  (B_AG / AB)       // 128  -> one wave
#define KSTR  88                // bf16 row stride (44 words: 16B-aligned + conflict-free)
#define RB    176               // row bytes

// ---- smem byte layout ----
#define SM_WHI   0               // 256*176 = 45056
#define SM_WLO   45056
#define SM_AHI   90112
#define SM_ALO   135168
#define SM_SMALL 180224          // 1280 floats
#define SM_TOTAL 185344
// smalls float offsets
#define O_EMBW 0
#define O_EMBB 640
#define O_LN1G 656
#define O_LN1B 696
#define O_GW   736    // float2[64]: (ln2g*w0, ln2g*w1) per j
#define O_SC   864    // SGW0, SGW1, CB0, CB1
#define O_BIAS 1024   // 256 floats, gate-interleaved (n' = 4j+gate)

// persistent state + prepped params. h/c stored [j][agent].
__device__ __align__(16) float          g_h[HD * B_AG];
__device__ __align__(16) float          g_c[HD * B_AG];
__device__ __align__(16) unsigned short g_Whi[NG * KSTR];
__device__ __align__(16) unsigned short g_Wlo[NG * KSTR];
__device__ __align__(16) float          g_smalls[1280];

// ---- helpers ----
__device__ __forceinline__ void cp16(unsigned s, const void* g) {
    asm volatile("cp.async.cg.shared.global [%0], [%1], 16;" :: "r"(s), "l"(g));
}
__device__ __forceinline__ unsigned pkbf(float a, float b) {
    __nv_bfloat162 t = __floats2bfloat162_rn(a, b);
    unsigned u; memcpy(&u, &t, 4); return u;
}
__device__ __forceinline__ void split(float v, float& hi, float& lo) {
    __nv_bfloat16 h = __float2bfloat16(v);
    hi = __bfloat162float(h);
    lo = v - hi;
}
__device__ __forceinline__ float tanhA(float x) {
    float r; asm("tanh.approx.f32 %0, %1;" : "=f"(r) : "f"(x)); return r;
}
__device__ __forceinline__ float sigmA(float x) {
    return fmaf(tanhA(0.5f * x), 0.5f, 0.5f);
}
__device__ __forceinline__ void ldsm4(unsigned& r0, unsigned& r1, unsigned& r2, unsigned& r3,
                                      unsigned addr) {
    asm volatile("ldmatrix.sync.aligned.m8n8.x4.shared.b16 {%0,%1,%2,%3}, [%4];"
                 : "=r"(r0), "=r"(r1), "=r"(r2), "=r"(r3) : "r"(addr));
}
__device__ __forceinline__ void ldsm2(unsigned& r0, unsigned& r1, unsigned addr) {
    asm volatile("ldmatrix.sync.aligned.m8n8.x2.shared.b16 {%0,%1}, [%2];"
                 : "=r"(r0), "=r"(r1) : "r"(addr));
}
__device__ __forceinline__ void mma16816(float& d0, float& d1, float& d2, float& d3,
                                         unsigned a0, unsigned a1, unsigned a2, unsigned a3,
                                         unsigned b0, unsigned b1) {
    asm volatile(
        "mma.sync.aligned.m16n8k16.row.col.f32.bf16.bf16.f32 "
        "{%0,%1,%2,%3}, {%4,%5,%6,%7}, {%8,%9}, {%0,%1,%2,%3};"
        : "+f"(d0), "+f"(d1), "+f"(d2), "+f"(d3)
        : "r"(a0), "r"(a1), "r"(a2), "r"(a3), "r"(b0), "r"(b1));
}

// ---------------- one-time prep ----------------
__global__ void prep_kernel(const float* __restrict__ decoderH,
                            const float* __restrict__ W_ih, const float* __restrict__ W_hh,
                            const float* __restrict__ b_ih, const float* __restrict__ b_hh,
                            const float* __restrict__ embW, const float* __restrict__ embB,
                            const float* __restrict__ ln1g, const float* __restrict__ ln1b,
                            const float* __restrict__ ln2g, const float* __restrict__ ln2b,
                            const float* __restrict__ h2pW, const float* __restrict__ h2pB)
{
    const int gid = blockIdx.x * blockDim.x + threadIdx.x;
    if (gid < NG * KD) {
        const int np = gid / KD;
        const int k  = gid % KD;
        const int n  = (np & 3) * HD + (np >> 2);   // gate-interleaved rows
        float w = (k < ED) ? W_ih[n * ED + k] : W_hh[n * HD + (k - ED)];
        float hi, lo; split(w, hi, lo);
        __nv_bfloat16 hb = __float2bfloat16(hi);
        __nv_bfloat16 lb = __float2bfloat16(lo);
        unsigned short hs, ls; memcpy(&hs, &hb, 2); memcpy(&ls, &lb, 2);
        g_Whi[np * KSTR + k] = hs;
        g_Wlo[np * KSTR + k] = ls;
    }
    if (gid < 1280) {
        float v;
        if (gid < 640)       v = embW[gid];
        else if (gid < 656)  v = embB[gid - 640];
        else if (gid < 696)  v = ln1g[gid - 656];
        else if (gid < 736)  v = ln1b[gid - 696];
        else if (gid < 864) {                       // gw pairs
            int q = gid - 736;
            int j = q >> 1;
            v = ln2g[j] * h2pW[(q & 1) * 64 + j];
        }
        else if (gid < 868) {                       // scalars
            int w = gid - 864;
            float acc = 0.f;
            if (w < 2) { for (int j = 0; j < 64; j++) acc += ln2g[j] * h2pW[w * 64 + j]; }
            else {
                int o = w - 2;
                for (int j = 0; j < 64; j++) acc += ln2b[j] * h2pW[o * 64 + j];
                acc += h2pB[o];
            }
            v = acc;
        }
        else if (gid >= 1024) {
            int np = gid - 1024;
            int n  = (np & 3) * HD + (np >> 2);
            v = b_ih[n] + b_hh[n];
        }
        else                 v = 0.f;
        g_smalls[gid] = v;
    }
    if (gid < B_AG * HD) {
        const int j = gid >> 15;
        const int b = gid & 32767;
        g_h[gid] = decoderH[b * HD + j];
        g_c[gid] = 0.f;
    }
}

// ---------------- per-step kernel ----------------
__global__ void __launch_bounds__(NTHR, 1)
lstm_step(int s,
          const float* __restrict__ trajAbs,
          float* __restrict__ out)
{
    extern __shared__ char sm[];
    float* sSm   = (float*)(sm + SM_SMALL);
    float* sBias = sSm + O_BIAS;

    const int tid  = threadIdx.x;
    const int wid  = tid >> 5;
    const int lane = tid & 31;
    const int b0   = blockIdx.x * AB;
    const unsigned sb = (unsigned)__cvta_generic_to_shared(sm);

    // kick W tile copies (90 KB), overlap with phase 1
    {
#pragma unroll
        for (int i = 0; i < 6; i++) {
            int c = tid + i * NTHR;
            if (c < 2816) {
                cp16(sb + SM_WHI + c * 16, (const char*)g_Whi + c * 16);
                cp16(sb + SM_WLO + c * 16, (const char*)g_Wlo + c * 16);
            }
        }
        asm volatile("cp.async.commit_group;");
    }
    if (tid < 320) ((float4*)sSm)[tid] = ((const float4*)g_smalls)[tid];
    __syncthreads();

    // ---------------- phase 1: gather + LN1 + embed + leaky -> A cols 0..15 ----
    {
        const int a  = tid >> 1;
        const int jt = tid & 1;
        const int b  = b0 + a;
        const int fbase = b * 40 + jt * 20;
        float raw[20];
#pragma unroll
        for (int u = 0; u < 20; u++) {
            int f   = fbase + u;
            int t   = f >> 16;
            int rem = f & 65535;
            int row = s + t;
            raw[u] = (row < OBS) ? trajAbs[row * ROW2 + rem]
                                 : out[(row - OBS) * ROW2 + rem];
        }
        float sum = 0.f, sq = 0.f;
#pragma unroll
        for (int u = 0; u < 20; u++) { sum += raw[u]; sq += raw[u] * raw[u]; }
        sum += __shfl_xor_sync(0xffffffffu, sum, 1);
        sq  += __shfl_xor_sync(0xffffffffu, sq, 1);
        const float mean = sum * 0.025f;
        const float var  = sq * 0.025f - mean * mean;
        const float rstd = rsqrtf(var + 1e-5f);

        float p[16];
#pragma unroll
        for (int e = 0; e < 16; e++) p[e] = 0.f;
#pragma unroll
        for (int u = 0; u < 20; u++) {
            int idx = jt * 20 + u;
            float xn = (raw[u] - mean) * rstd * sSm[O_LN1G + idx] + sSm[O_LN1B + idx];
#pragma unroll
            for (int e = 0; e < 16; e++) p[e] += xn * sSm[O_EMBW + e * 40 + idx];
        }
#pragma unroll
        for (int e = 0; e < 16; e++)
            p[e] += __shfl_xor_sync(0xffffffffu, p[e], 1);

#pragma unroll
        for (int i = 0; i < 4; i++) {
            int e = jt * 8 + 2 * i;
            float v0 = p[e]   + sSm[O_EMBB + e];
            float v1 = p[e+1] + sSm[O_EMBB + e + 1];
            v0 = v0 > 0.f ? v0 : 0.01f * v0;
            v1 = v1 > 0.f ? v1 : 0.01f * v1;
            float h0, l0, h1, l1;
            split(v0, h0, l0); split(v1, h1, l1);
            unsigned off = a * RB + e * 2;
            *(unsigned*)(sm + SM_AHI + off) = pkbf(h0, h1);
            *(unsigned*)(sm + SM_ALO + off) = pkbf(l0, l1);
        }
    }
    // h -> A cols 16..79
    {
#pragma unroll
        for (int it = 0; it < 16; it++) {
            int idx = tid + it * NTHR;
            int a  = idx & 255;
            int j  = (idx >> 8) * 2;
            float v0 = g_h[j * B_AG + b0 + a];
            float v1 = g_h[(j + 1) * B_AG + b0 + a];
            float h0, l0, h1, l1;
            split(v0, h0, l0); split(v1, h1, l1);
            unsigned off = a * RB + (16 + j) * 2;
            *(unsigned*)(sm + SM_AHI + off) = pkbf(h0, h1);
            *(unsigned*)(sm + SM_ALO + off) = pkbf(l0, l1);
        }
    }
    asm volatile("cp.async.wait_group 0;");
    __syncthreads();

    // ---------------- A-fragment preload via ldmatrix (m-tile = wid) -----------
    const int g   = lane >> 2;
    const int tig = lane & 3;
    unsigned ahi[5][4], alo[5][4];
    {
        unsigned abase = (wid * 16 + ((lane >> 3) & 1) * 8 + (lane & 7)) * RB
                       + (lane >> 4) * 16;
#pragma unroll
        for (int kt = 0; kt < 5; kt++) {
            ldsm4(ahi[kt][0], ahi[kt][1], ahi[kt][2], ahi[kt][3],
                  sb + SM_AHI + abase + kt * 32);
            ldsm4(alo[kt][0], alo[kt][1], alo[kt][2], alo[kt][3],
                  sb + SM_ALO + abase + kt * 32);
        }
    }

    // ---------------- GEMM + fused LSTM cell + fused LN2/h2p -------------------
    const int oddp  = tig & 1;
    const int a_loc = wid * 16 + g + (oddp ? 8 : 0);
    const int bglob = b0 + a_loc;
    // B ldmatrix lane addresses
    unsigned brow4 = (lane & 7) * RB + (lane >> 3) * 16;              // quads 0-7
    unsigned brow2 = (lane & 7) * RB + 128 + ((lane >> 3) & 1) * 16;  // quads 8,9

    float sum_h = 0.f, sq_h = 0.f, S0 = 0.f, S1 = 0.f;

#pragma unroll 1
    for (int nt = 0; nt < 32; nt++) {
        unsigned bh[10], bl[10];
        ldsm4(bh[0], bh[1], bh[2], bh[3], sb + SM_WHI + brow4);
        ldsm4(bh[4], bh[5], bh[6], bh[7], sb + SM_WHI + brow4 + 64);
        ldsm2(bh[8], bh[9],              sb + SM_WHI + brow2);
        ldsm4(bl[0], bl[1], bl[2], bl[3], sb + SM_WLO + brow4);
        ldsm4(bl[4], bl[5], bl[6], bl[7], sb + SM_WLO + brow4 + 64);
        ldsm2(bl[8], bl[9],              sb + SM_WLO + brow2);
        brow4 += 8 * RB; brow2 += 8 * RB;

        float d0 = 0.f, d1 = 0.f, d2 = 0.f, d3 = 0.f;
#pragma unroll
        for (int kt = 0; kt < 5; kt++) {
            mma16816(d0, d1, d2, d3, ahi[kt][0], ahi[kt][1], ahi[kt][2], ahi[kt][3],
                     bh[2*kt], bh[2*kt+1]);
            mma16816(d0, d1, d2, d3, ahi[kt][0], ahi[kt][1], ahi[kt][2], ahi[kt][3],
                     bl[2*kt], bl[2*kt+1]);
            mma16816(d0, d1, d2, d3, alo[kt][0], alo[kt][1], alo[kt][2], alo[kt][3],
                     bh[2*kt], bh[2*kt+1]);
        }
        // lane exchange: one full (i,f,g,o) cell per lane
        float r0 = __shfl_xor_sync(0xffffffffu, d0, 1);
        float r1 = __shfl_xor_sync(0xffffffffu, d1, 1);
        float r2 = __shfl_xor_sync(0xffffffffu, d2, 1);
        float r3 = __shfl_xor_sync(0xffffffffu, d3, 1);
        float iv = oddp ? r2 : d0;
        float fv = oddp ? r3 : d1;
        float gv = oddp ? d2 : r0;
        float ov = oddp ? d3 : r1;
        const int jj = 2 * nt + (tig >> 1);
        float4 bias = *(const float4*)(sBias + 4 * jj);
        iv += bias.x; fv += bias.y; gv += bias.z; ov += bias.w;

        const int cidx = jj * B_AG + bglob;
        float c_old = g_c[cidx];
        float ig = sigmA(iv);
        float fg = sigmA(fv);
        float og = sigmA(ov);
        float gg = tanhA(gv);
        float c2 = fmaf(fg, c_old, ig * gg);
        float hv = og * tanhA(c2);
        g_c[cidx] = c2;
        g_h[cidx] = hv;

        sum_h += hv;
        sq_h   = fmaf(hv, hv, sq_h);
        float2 gw = *(const float2*)(sSm + O_GW + 2 * jj);
        S0 = fmaf(hv, gw.x, S0);
        S1 = fmaf(hv, gw.y, S1);
    }

    // reduce across the 2 lanes sharing this agent (tig ^ 2)
    sum_h += __shfl_xor_sync(0xffffffffu, sum_h, 2);
    sq_h  += __shfl_xor_sync(0xffffffffu, sq_h, 2);
    S0    += __shfl_xor_sync(0xffffffffu, S0, 2);
    S1    += __shfl_xor_sync(0xffffffffu, S1, 2);

    if (tig < 2) {
        const float m    = sum_h * 0.015625f;
        const float var  = sq_h * 0.015625f - m * m;
        const float rstd = rsqrtf(var + 1e-5f);
        float2 r = make_float2(rstd * (S0 - m * sSm[O_SC + 0]) + sSm[O_SC + 2],
                               rstd * (S1 - m * sSm[O_SC + 1]) + sSm[O_SC + 3]);
        *(float2*)(out + s * ROW2 + bglob * 2) = r;
    }
}

extern "C" void kernel_launch(void* const* d_in, const int* in_sizes, int n_in,
                              void* d_out, int out_size)
{
    const float* trajAbs  = (const float*)d_in[0];
    const float* decoderH = (const float*)d_in[2];
    const float* W_ih = (const float*)d_in[3];
    const float* W_hh = (const float*)d_in[4];
    const float* b_ih = (const float*)d_in[5];
    const float* b_hh = (const float*)d_in[6];
    const float* embW = (const float*)d_in[7];
    const float* embB = (const float*)d_in[8];
    const float* h2pW = (const float*)d_in[9];
    const float* h2pB = (const float*)d_in[10];
    const float* ln1g = (const float*)d_in[11];
    const float* ln1b = (const float*)d_in[12];
    const float* ln2g = (const float*)d_in[13];
    const float* ln2b = (const float*)d_in[14];
    float* out = (float*)d_out;

    prep_kernel<<<(B_AG * HD + 255) / 256, 256>>>(
        decoderH, W_ih, W_hh, b_ih, b_hh, embW, embB,
        ln1g, ln1b, ln2g, ln2b, h2pW, h2pB);

    cudaFuncSetAttribute(lstm_step, cudaFuncAttributeMaxDynamicSharedMemorySize,
                         SM_TOTAL);

    for (int s = 0; s < PRED; s++) {
        lstm_step<<<NBLK, NTHR, SM_TOTAL>>>(s, trajAbs, out);
    }
}

// round 10
// speedup vs baseline: 2.2852x; 1.0396x over previous
#include <cuda_runtime.h>
#include <cuda_bf16.h>
#include <cstring>

#define OBS   20
#define PRED  30
#define B_AG  32768
#define ROW2  65536
#define HD    64
#define ED    16
#define KD    80
#define NG    256
#define AB    256               // agents per block
#define NTHR  512
#define NBLK  (B_AG / AB)       // 128 blocks -> all co-resident (148 SMs)
#define KSTR  88                // bf16 row stride (44 words: 16B-aligned + conflict-free)
#define RB    176               // row bytes

// ---- smem byte layout ----
#define SM_WHI   0               // 256*176 = 45056
#define SM_WLO   45056
#define SM_AHI   90112
#define SM_ALO   135168
#define SM_SMALL 180224          // 1280 floats
#define SM_TOTAL 185344
// smalls float offsets
#define O_EMBW 0
#define O_EMBB 640
#define O_LN1G 656
#define O_LN1B 696
#define O_GW   736    // float2[64]: (ln2g*w0, ln2g*w1) per j
#define O_SC   864    // SGW0, SGW1, CB0, CB1
#define O_BIAS 1024   // 256 floats, gate-interleaved (n' = 4j+gate)

// persistent state + prepped params. c stored [j][agent].
__device__ __align__(16) float          g_c[HD * B_AG];
__device__ __align__(16) unsigned short g_Whi[NG * KSTR];
__device__ __align__(16) unsigned short g_Wlo[NG * KSTR];
__device__ __align__(16) float          g_smalls[1280];
__device__ unsigned g_bar;     // grid barrier counter (reset by prep each replay)

// ---- helpers ----
__device__ __forceinline__ void cp16(unsigned s, const void* g) {
    asm volatile("cp.async.cg.shared.global [%0], [%1], 16;" :: "r"(s), "l"(g));
}
__device__ __forceinline__ unsigned pkbf(float a, float b) {
    __nv_bfloat162 t = __floats2bfloat162_rn(a, b);
    unsigned u; memcpy(&u, &t, 4); return u;
}
__device__ __forceinline__ void split(float v, float& hi, float& lo) {
    __nv_bfloat16 h = __float2bfloat16(v);
    hi = __bfloat162float(h);
    lo = v - hi;
}
__device__ __forceinline__ float tanhA(float x) {
    float r; asm("tanh.approx.f32 %0, %1;" : "=f"(r) : "f"(x)); return r;
}
__device__ __forceinline__ float sigmA(float x) {
    return fmaf(tanhA(0.5f * x), 0.5f, 0.5f);
}
__device__ __forceinline__ void ldsm4(unsigned& r0, unsigned& r1, unsigned& r2, unsigned& r3,
                                      unsigned addr) {
    asm volatile("ldmatrix.sync.aligned.m8n8.x4.shared.b16 {%0,%1,%2,%3}, [%4];"
                 : "=r"(r0), "=r"(r1), "=r"(r2), "=r"(r3) : "r"(addr));
}
__device__ __forceinline__ void ldsm2(unsigned& r0, unsigned& r1, unsigned addr) {
    asm volatile("ldmatrix.sync.aligned.m8n8.x2.shared.b16 {%0,%1}, [%2];"
                 : "=r"(r0), "=r"(r1) : "r"(addr));
}
__device__ __forceinline__ void mma16816(float& d0, float& d1, float& d2, float& d3,
                                         unsigned a0, unsigned a1, unsigned a2, unsigned a3,
                                         unsigned b0, unsigned b1) {
    asm volatile(
        "mma.sync.aligned.m16n8k16.row.col.f32.bf16.bf16.f32 "
        "{%0,%1,%2,%3}, {%4,%5,%6,%7}, {%8,%9}, {%0,%1,%2,%3};"
        : "+f"(d0), "+f"(d1), "+f"(d2), "+f"(d3)
        : "r"(a0), "r"(a1), "r"(a2), "r"(a3), "r"(b0), "r"(b1));
}
__device__ __forceinline__ unsigned ldvol(unsigned* p) {
    unsigned v;
    asm volatile("ld.volatile.global.u32 %0, [%1];" : "=r"(v) : "l"(p));
    return v;
}

// ---------------- one-time prep ----------------
__global__ void prep_kernel(const float* __restrict__ W_ih, const float* __restrict__ W_hh,
                            const float* __restrict__ b_ih, const float* __restrict__ b_hh,
                            const float* __restrict__ embW, const float* __restrict__ embB,
                            const float* __restrict__ ln1g, const float* __restrict__ ln1b,
                            const float* __restrict__ ln2g, const float* __restrict__ ln2b,
                            const float* __restrict__ h2pW, const float* __restrict__ h2pB)
{
    const int gid = blockIdx.x * blockDim.x + threadIdx.x;
    if (gid == 0) g_bar = 0;
    if (gid < NG * KD) {
        const int np = gid / KD;
        const int k  = gid % KD;
        const int n  = (np & 3) * HD + (np >> 2);   // gate-interleaved rows
        float w = (k < ED) ? W_ih[n * ED + k] : W_hh[n * HD + (k - ED)];
        float hi, lo; split(w, hi, lo);
        __nv_bfloat16 hb = __float2bfloat16(hi);
        __nv_bfloat16 lb = __float2bfloat16(lo);
        unsigned short hs, ls; memcpy(&hs, &hb, 2); memcpy(&ls, &lb, 2);
        g_Whi[np * KSTR + k] = hs;
        g_Wlo[np * KSTR + k] = ls;
    }
    if (gid < 1280) {
        float v;
        if (gid < 640)       v = embW[gid];
        else if (gid < 656)  v = embB[gid - 640];
        else if (gid < 696)  v = ln1g[gid - 656];
        else if (gid < 736)  v = ln1b[gid - 696];
        else if (gid < 864) {                       // gw pairs
            int q = gid - 736;
            int j = q >> 1;
            v = ln2g[j] * h2pW[(q & 1) * 64 + j];
        }
        else if (gid < 868) {                       // scalars
            int w = gid - 864;
            float acc = 0.f;
            if (w < 2) { for (int j = 0; j < 64; j++) acc += ln2g[j] * h2pW[w * 64 + j]; }
            else {
                int o = w - 2;
                for (int j = 0; j < 64; j++) acc += ln2b[j] * h2pW[o * 64 + j];
                acc += h2pB[o];
            }
            v = acc;
        }
        else if (gid >= 1024) {
            int np = gid - 1024;
            int n  = (np & 3) * HD + (np >> 2);
            v = b_ih[n] + b_hh[n];
        }
        else                 v = 0.f;
        g_smalls[gid] = v;
    }
    if (gid < B_AG * HD) g_c[gid] = 0.f;   // [j][agent], zero-init
}

// ---------------- persistent kernel: all 30 steps ----------------
__global__ void __launch_bounds__(NTHR, 1)
lstm_persist(const float* __restrict__ trajAbs,
             const float* __restrict__ decoderH,
             float* __restrict__ out)
{
    extern __shared__ char sm[];
    float* sSm   = (float*)(sm + SM_SMALL);
    float* sBias = sSm + O_BIAS;

    const int tid  = threadIdx.x;
    const int lane = tid & 31;
    const int wid  = tid >> 5;
    const int b0   = blockIdx.x * AB;
    const unsigned sb = (unsigned)__cvta_generic_to_shared(sm);

    // ---- one-time: W tiles (90 KB), smalls, initial h -> A cols 16..79 ----
    {
#pragma unroll
        for (int i = 0; i < 6; i++) {
            int c = tid + i * NTHR;
            if (c < 2816) {
                cp16(sb + SM_WHI + c * 16, (const char*)g_Whi + c * 16);
                cp16(sb + SM_WLO + c * 16, (const char*)g_Wlo + c * 16);
            }
        }
        asm volatile("cp.async.commit_group;");
    }
    if (tid < 320) ((float4*)sSm)[tid] = ((const float4*)g_smalls)[tid];
    {
        // decoderH: (1, B, H) row-major -> agent-major float4 loads
#pragma unroll
        for (int it = 0; it < 8; it++) {
            int idx = tid + it * NTHR;       // 4096 float4s
            int a = idx >> 4;
            int j = (idx & 15) * 4;
            float4 hv = *(const float4*)(decoderH + (b0 + a) * HD + j);
            float h0,l0,h1,l1,h2,l2,h3,l3;
            split(hv.x,h0,l0); split(hv.y,h1,l1); split(hv.z,h2,l2); split(hv.w,h3,l3);
            unsigned off = a * RB + (16 + j) * 2;
            *(unsigned*)(sm + SM_AHI + off)     = pkbf(h0, h1);
            *(unsigned*)(sm + SM_AHI + off + 4) = pkbf(h2, h3);
            *(unsigned*)(sm + SM_ALO + off)     = pkbf(l0, l1);
            *(unsigned*)(sm + SM_ALO + off + 4) = pkbf(l2, l3);
        }
    }
    asm volatile("cp.async.wait_group 0;");
    __syncthreads();

    // invariant lane constants
    const int g    = lane >> 2;
    const int tig  = lane & 3;
    const int oddp = tig & 1;
    const int a_loc = wid * 16 + g + (oddp ? 8 : 0);
    const int bglob = b0 + a_loc;
    const unsigned abase = (wid * 16 + ((lane >> 3) & 1) * 8 + (lane & 7)) * RB
                         + (lane >> 4) * 16;
    const unsigned brow4_0 = (lane & 7) * RB + (lane >> 3) * 16;
    const unsigned brow2_0 = (lane & 7) * RB + 128 + ((lane >> 3) & 1) * 16;
    const int jj_base = tig >> 1;

    for (int s = 0; s < PRED; s++) {
        // ---------------- phase 1: gather + LN1 + embed + leaky -> A cols 0..15 ----
        {
            const int a  = tid >> 1;
            const int jt = tid & 1;
            const int b  = b0 + a;
            const int fbase = b * 40 + jt * 20;
            float raw[20];
#pragma unroll
            for (int u = 0; u < 20; u++) {
                int f   = fbase + u;
                int t   = f >> 16;
                int rem = f & 65535;
                int row = s + t;
                raw[u] = (row < OBS) ? trajAbs[row * ROW2 + rem]
                                     : out[(row - OBS) * ROW2 + rem];
            }
            float sum = 0.f, sq = 0.f;
#pragma unroll
            for (int u = 0; u < 20; u++) { sum += raw[u]; sq += raw[u] * raw[u]; }
            sum += __shfl_xor_sync(0xffffffffu, sum, 1);
            sq  += __shfl_xor_sync(0xffffffffu, sq, 1);
            const float mean = sum * 0.025f;
            const float var  = sq * 0.025f - mean * mean;
            const float rstd = rsqrtf(var + 1e-5f);

            float p[16];
#pragma unroll
            for (int e = 0; e < 16; e++) p[e] = 0.f;
#pragma unroll
            for (int u = 0; u < 20; u++) {
                int idx = jt * 20 + u;
                float xn = (raw[u] - mean) * rstd * sSm[O_LN1G + idx] + sSm[O_LN1B + idx];
#pragma unroll
                for (int e = 0; e < 16; e++) p[e] += xn * sSm[O_EMBW + e * 40 + idx];
            }
#pragma unroll
            for (int e = 0; e < 16; e++)
                p[e] += __shfl_xor_sync(0xffffffffu, p[e], 1);

#pragma unroll
            for (int i = 0; i < 4; i++) {
                int e = jt * 8 + 2 * i;
                float v0 = p[e]   + sSm[O_EMBB + e];
                float v1 = p[e+1] + sSm[O_EMBB + e + 1];
                v0 = v0 > 0.f ? v0 : 0.01f * v0;
                v1 = v1 > 0.f ? v1 : 0.01f * v1;
                float h0, l0, h1, l1;
                split(v0, h0, l0); split(v1, h1, l1);
                unsigned off = a * RB + e * 2;
                *(unsigned*)(sm + SM_AHI + off) = pkbf(h0, h1);
                *(unsigned*)(sm + SM_ALO + off) = pkbf(l0, l1);
            }
        }
        __syncthreads();

        // ---------------- A-fragment preload via ldmatrix -----------------------
        unsigned ahi[5][4], alo[5][4];
#pragma unroll
        for (int kt = 0; kt < 5; kt++) {
            ldsm4(ahi[kt][0], ahi[kt][1], ahi[kt][2], ahi[kt][3],
                  sb + SM_AHI + abase + kt * 32);
            ldsm4(alo[kt][0], alo[kt][1], alo[kt][2], alo[kt][3],
                  sb + SM_ALO + abase + kt * 32);
        }
        __syncthreads();

        // ---------------- GEMM + fused LSTM cell + fused LN2/h2p ----------------
        unsigned brow4 = brow4_0, brow2 = brow2_0;
        float sum_h = 0.f, sq_h = 0.f, S0 = 0.f, S1 = 0.f;

#pragma unroll 1
        for (int nt = 0; nt < 32; nt++) {
            const int jj   = 2 * nt + jj_base;
            const int cidx = jj * B_AG + bglob;
            float c_old = g_c[cidx];

            unsigned bh[10], bl[10];
            ldsm4(bh[0], bh[1], bh[2], bh[3], sb + SM_WHI + brow4);
            ldsm4(bh[4], bh[5], bh[6], bh[7], sb + SM_WHI + brow4 + 64);
            ldsm2(bh[8], bh[9],              sb + SM_WHI + brow2);
            ldsm4(bl[0], bl[1], bl[2], bl[3], sb + SM_WLO + brow4);
            ldsm4(bl[4], bl[5], bl[6], bl[7], sb + SM_WLO + brow4 + 64);
            ldsm2(bl[8], bl[9],              sb + SM_WLO + brow2);
            brow4 += 8 * RB; brow2 += 8 * RB;

            float d0 = 0.f, d1 = 0.f, d2 = 0.f, d3 = 0.f;
#pragma unroll
            for (int kt = 0; kt < 5; kt++) {
                mma16816(d0, d1, d2, d3, ahi[kt][0], ahi[kt][1], ahi[kt][2], ahi[kt][3],
                         bh[2*kt], bh[2*kt+1]);
                mma16816(d0, d1, d2, d3, ahi[kt][0], ahi[kt][1], ahi[kt][2], ahi[kt][3],
                         bl[2*kt], bl[2*kt+1]);
                mma16816(d0, d1, d2, d3, alo[kt][0], alo[kt][1], alo[kt][2], alo[kt][3],
                         bh[2*kt], bh[2*kt+1]);
            }
            // lane exchange: one full (i,f,g,o) cell per lane
            float r0 = __shfl_xor_sync(0xffffffffu, d0, 1);
            float r1 = __shfl_xor_sync(0xffffffffu, d1, 1);
            float r2 = __shfl_xor_sync(0xffffffffu, d2, 1);
            float r3 = __shfl_xor_sync(0xffffffffu, d3, 1);
            float iv = oddp ? r2 : d0;
            float fv = oddp ? r3 : d1;
            float gv = oddp ? d2 : r0;
            float ov = oddp ? d3 : r1;
            float4 bias = *(const float4*)(sBias + 4 * jj);
            iv += bias.x; fv += bias.y; gv += bias.z; ov += bias.w;

            float ig = sigmA(iv);
            float fg = sigmA(fv);
            float og = sigmA(ov);
            float gg = tanhA(gv);
            float c2 = fmaf(fg, c_old, ig * gg);
            float hv = og * tanhA(c2);
            g_c[cidx] = c2;

            // write h split directly into A tile (cols 16..79) for next step
            float hh, hl;
            split(hv, hh, hl);
            unsigned hoff = a_loc * RB + (16 + jj) * 2;
            *(__nv_bfloat16*)(sm + SM_AHI + hoff) = __float2bfloat16(hh);
            *(__nv_bfloat16*)(sm + SM_ALO + hoff) = __float2bfloat16(hl);

            sum_h += hv;
            sq_h   = fmaf(hv, hv, sq_h);
            float2 gw = *(const float2*)(sSm + O_GW + 2 * jj);
            S0 = fmaf(hv, gw.x, S0);
            S1 = fmaf(hv, gw.y, S1);
        }

        // reduce across the 2 lanes sharing this agent (tig ^ 2)
        sum_h += __shfl_xor_sync(0xffffffffu, sum_h, 2);
        sq_h  += __shfl_xor_sync(0xffffffffu, sq_h, 2);
        S0    += __shfl_xor_sync(0xffffffffu, S0, 2);
        S1    += __shfl_xor_sync(0xffffffffu, S1, 2);

        if (tig < 2) {
            const float m    = sum_h * 0.015625f;
            const float var  = sq_h * 0.015625f - m * m;
            const float rstd = rsqrtf(var + 1e-5f);
            float2 r = make_float2(rstd * (S0 - m * sSm[O_SC + 0]) + sSm[O_SC + 2],
                                   rstd * (S1 - m * sSm[O_SC + 1]) + sSm[O_SC + 3]);
            *(float2*)(out + s * ROW2 + bglob * 2) = r;
        }

        // ---------------- grid barrier (skip after last step) --------------------
        if (s < PRED - 1) {
            __threadfence();
            __syncthreads();
            if (tid == 0) {
                atomicAdd(&g_bar, 1u);
                const unsigned target = (unsigned)(s + 1) * (unsigned)gridDim.x;
                while (ldvol(&g_bar) < target) __nanosleep(64);
            }
            __syncthreads();
            __threadfence();
        }
    }
}

extern "C" void kernel_launch(void* const* d_in, const int* in_sizes, int n_in,
                              void* d_out, int out_size)
{
    const float* trajAbs  = (const float*)d_in[0];
    const float* decoderH = (const float*)d_in[2];
    const float* W_ih = (const float*)d_in[3];
    const float* W_hh = (const float*)d_in[4];
    const float* b_ih = (const float*)d_in[5];
    const float* b_hh = (const float*)d_in[6];
    const float* embW = (const float*)d_in[7];
    const float* embB = (const float*)d_in[8];
    const float* h2pW = (const float*)d_in[9];
    const float* h2pB = (const float*)d_in[10];
    const float* ln1g = (const float*)d_in[11];
    const float* ln1b = (const float*)d_in[12];
    const float* ln2g = (const float*)d_in[13];
    const float* ln2b = (const float*)d_in[14];
    float* out = (float*)d_out;

    prep_kernel<<<(B_AG * HD + 255) / 256, 256>>>(
        W_ih, W_hh, b_ih, b_hh, embW, embB,
        ln1g, ln1b, ln2g, ln2b, h2pW, h2pB);

    cudaFuncSetAttribute(lstm_persist, cudaFuncAttributeMaxDynamicSharedMemorySize,
                         SM_TOTAL);

    lstm_persist<<<NBLK, NTHR, SM_TOTAL>>>(trajAbs, decoderH, out);
}